// round 2
// baseline (speedup 1.0000x reference)
#include <cuda_runtime.h>
#include <math.h>

#define BSZ   2
#define CH    256
#define SCTX  1024
#define NH    8
#define HD    32
#define TTOT  8525

// ---------------- scratch (__device__ globals; no runtime allocation) --------
__device__ float g_v    [BSZ * TTOT * CH];
__device__ float g_vn   [BSZ * TTOT * CH];
__device__ float g_q    [BSZ * TTOT * CH];
__device__ float g_cn   [BSZ * SCTX * CH];
__device__ float g_k    [BSZ * SCTX * CH];
__device__ float g_val  [BSZ * SCTX * CH];
__device__ float g_o    [BSZ * TTOT * CH];
__device__ float g_delta[BSZ * TTOT * CH];
__device__ float g_g1   [BSZ * TTOT * (CH / 2)];
__device__ float g_nv   [BSZ * TTOT * CH];

// ---------------- gather: (b, c, hw) -> v (b, t, c), tiled transpose ---------
__global__ void gather_kernel(const float* __restrict__ in, float* __restrict__ v,
                              int hw, int tstart)
{
    __shared__ float tile[32][33];
    int b   = blockIdx.z;
    int ch0 = blockIdx.y * 32;
    int p0  = blockIdx.x * 32;
    int tx = threadIdx.x, ty = threadIdx.y;   // 32 x 8
#pragma unroll
    for (int i = 0; i < 4; i++) {
        int ch = ch0 + ty + i * 8;
        int p  = p0 + tx;
        if (p < hw)
            tile[ty + i * 8][tx] = in[((size_t)(b * CH + ch)) * hw + p];
    }
    __syncthreads();
#pragma unroll
    for (int i = 0; i < 4; i++) {
        int p  = p0 + ty + i * 8;
        int ch = ch0 + tx;
        if (p < hw)
            v[((size_t)(b * TTOT + tstart + p)) * CH + ch] = tile[tx][ty + i * 8];
    }
}

// ---------------- scatter: nv (b, t, c) -> out level block (b, c, hw) --------
__global__ void scatter_kernel(const float* __restrict__ nv, float* __restrict__ out,
                               int hw, int tstart, size_t obase)
{
    __shared__ float tile[32][33];
    int b   = blockIdx.z;
    int ch0 = blockIdx.y * 32;
    int p0  = blockIdx.x * 32;
    int tx = threadIdx.x, ty = threadIdx.y;
#pragma unroll
    for (int i = 0; i < 4; i++) {
        int p  = p0 + ty + i * 8;
        int ch = ch0 + tx;
        if (p < hw)
            tile[ty + i * 8][tx] = nv[((size_t)(b * TTOT + tstart + p)) * CH + ch];
    }
    __syncthreads();
#pragma unroll
    for (int i = 0; i < 4; i++) {
        int ch = ch0 + ty + i * 8;
        int p  = p0 + tx;
        if (p < hw)
            out[obase + ((size_t)(b * CH + ch)) * hw + p] = tile[tx][ty + i * 8];
    }
}

// ---------------- layernorm over last dim (256), one block per row -----------
__global__ void ln_kernel(const float* __restrict__ x, const float* __restrict__ gg,
                          const float* __restrict__ bb, float* __restrict__ y)
{
    int row = blockIdx.x;
    int tid = threadIdx.x;          // 256 threads
    float v = x[(size_t)row * CH + tid];
    float s = v, sq = v * v;
#pragma unroll
    for (int o = 16; o > 0; o >>= 1) {
        s  += __shfl_xor_sync(0xffffffffu, s,  o);
        sq += __shfl_xor_sync(0xffffffffu, sq, o);
    }
    __shared__ float ss[8], ssq[8];
    int w = tid >> 5, l = tid & 31;
    if (l == 0) { ss[w] = s; ssq[w] = sq; }
    __syncthreads();
    if (w == 0) {
        float s2 = ss[l & 7], q2 = ssq[l & 7];
#pragma unroll
        for (int o = 4; o > 0; o >>= 1) {
            s2 += __shfl_xor_sync(0xffffffffu, s2, o);
            q2 += __shfl_xor_sync(0xffffffffu, q2, o);
        }
        if (l == 0) { ss[0] = s2; ssq[0] = q2; }
    }
    __syncthreads();
    float mean = ss[0] * (1.0f / CH);
    float var  = ssq[0] * (1.0f / CH) - mean * mean;
    y[(size_t)row * CH + tid] = (v - mean) * rsqrtf(var + 1e-5f) * gg[tid] + bb[tid];
}

// ---------------- generic GEMM: C = epi(A @ W + bias) ------------------------
// EPI 0: +bias   1: (+bias)*scale   2: relu(+bias)   3: vres + tanh(+bias)*dres
#define GBM 64
#define GBN 64
#define GBK 32

template <int EPI>
__global__ void gemm_kernel(const float* __restrict__ A, const float* __restrict__ W,
                            const float* __restrict__ bias, float* __restrict__ Cm,
                            int M, int N, int K, float scale,
                            const float* __restrict__ vres, const float* __restrict__ dres)
{
    __shared__ float As[GBM][GBK + 1];
    __shared__ float Bs[GBK][GBN + 2];
    int bm  = blockIdx.y * GBM;
    int bn  = blockIdx.x * GBN;
    int tid = threadIdx.x;                 // 256
    int tr  = (tid >> 4) << 2;             // 0..60
    int tc  = (tid & 15) << 2;             // 0..60
    float acc[4][4] = {};
    for (int k0 = 0; k0 < K; k0 += GBK) {
#pragma unroll
        for (int e = 0; e < 8; e++) {
            int lin = tid + e * 256;
            int r = lin >> 5, c = lin & 31;
            int gr = bm + r;
            As[r][c] = (gr < M) ? A[(size_t)gr * K + k0 + c] : 0.0f;
        }
#pragma unroll
        for (int e = 0; e < 8; e++) {
            int lin = tid + e * 256;
            int r = lin >> 6, c = lin & 63;
            Bs[r][c] = W[(size_t)(k0 + r) * N + bn + c];
        }
        __syncthreads();
#pragma unroll
        for (int k = 0; k < GBK; k++) {
            float a0 = As[tr + 0][k], a1 = As[tr + 1][k];
            float a2 = As[tr + 2][k], a3 = As[tr + 3][k];
            float b0 = Bs[k][tc + 0], b1 = Bs[k][tc + 1];
            float b2 = Bs[k][tc + 2], b3 = Bs[k][tc + 3];
            acc[0][0] += a0 * b0; acc[0][1] += a0 * b1; acc[0][2] += a0 * b2; acc[0][3] += a0 * b3;
            acc[1][0] += a1 * b0; acc[1][1] += a1 * b1; acc[1][2] += a1 * b2; acc[1][3] += a1 * b3;
            acc[2][0] += a2 * b0; acc[2][1] += a2 * b1; acc[2][2] += a2 * b2; acc[2][3] += a2 * b3;
            acc[3][0] += a3 * b0; acc[3][1] += a3 * b1; acc[3][2] += a3 * b2; acc[3][3] += a3 * b3;
        }
        __syncthreads();
    }
#pragma unroll
    for (int i = 0; i < 4; i++) {
        int gr = bm + tr + i;
        if (gr >= M) continue;
#pragma unroll
        for (int j = 0; j < 4; j++) {
            int gc = bn + tc + j;
            float val = acc[i][j] + bias[gc];
            if (EPI == 1) val *= scale;
            if (EPI == 2) val = fmaxf(val, 0.0f);
            if (EPI == 3) {
                size_t ridx = (size_t)gr * 256 + gc;   // vres/dres have N=256
                val = vres[ridx] + tanhf(val) * dres[ridx];
            }
            Cm[(size_t)gr * N + gc] = val;
        }
    }
}

// ---------------- flash attention: Q(b,t,c) K/V(b,s,c), head = chan slice ----
#define AQ 64
#define AS 64

__global__ void attn_kernel(const float* __restrict__ Qb, const float* __restrict__ Kb,
                            const float* __restrict__ Vb, const int* __restrict__ mask,
                            float* __restrict__ Ob)
{
    __shared__ float Qs[AQ][HD + 1];
    __shared__ float Ks[AS][HD + 1];
    __shared__ float Vs[AS][HD];
    __shared__ float Ls[AQ][AS + 1];
    __shared__ float madd[AS];

    int b  = blockIdx.z;
    int h  = blockIdx.y;
    int t0 = blockIdx.x * AQ;
    int tid = threadIdx.x;               // 256

    // load Q tile (zero-pad beyond T)
#pragma unroll
    for (int e = 0; e < 8; e++) {
        int lin = tid + e * 256;
        int r = lin >> 5, c = lin & 31;
        int t = t0 + r;
        Qs[r][c] = (t < TTOT) ? Qb[((size_t)(b * TTOT + t)) * CH + h * HD + c] : 0.0f;
    }

    int rr = (tid >> 4) << 2;            // logit micro-tile rows
    int cc = (tid & 15) << 2;            // logit micro-tile cols
    int r  = tid >> 2;                   // softmax/PV row owner
    int g  = tid & 3;                    // group of 4 threads per row

    float m = -INFINITY, l = 0.0f;
    float acc[8] = {};

    for (int s0 = 0; s0 < SCTX; s0 += AS) {
#pragma unroll
        for (int e = 0; e < 8; e++) {
            int lin = tid + e * 256;
            int sr = lin >> 5, sc = lin & 31;
            size_t gidx = ((size_t)(b * SCTX + s0 + sr)) * CH + h * HD + sc;
            Ks[sr][sc] = Kb[gidx];
            Vs[sr][sc] = Vb[gidx];
        }
        if (tid < AS)
            madd[tid] = mask[b * SCTX + s0 + tid] ? 1.0f : -9e15f;
        __syncthreads();

        // logits: 4x4 micro-tile per thread
        float lg[4][4] = {};
#pragma unroll
        for (int k = 0; k < HD; k++) {
            float a0 = Qs[rr + 0][k], a1 = Qs[rr + 1][k];
            float a2 = Qs[rr + 2][k], a3 = Qs[rr + 3][k];
            float k0 = Ks[cc + 0][k], k1 = Ks[cc + 1][k];
            float k2 = Ks[cc + 2][k], k3 = Ks[cc + 3][k];
            lg[0][0] += a0 * k0; lg[0][1] += a0 * k1; lg[0][2] += a0 * k2; lg[0][3] += a0 * k3;
            lg[1][0] += a1 * k0; lg[1][1] += a1 * k1; lg[1][2] += a1 * k2; lg[1][3] += a1 * k3;
            lg[2][0] += a2 * k0; lg[2][1] += a2 * k1; lg[2][2] += a2 * k2; lg[2][3] += a2 * k3;
            lg[3][0] += a3 * k0; lg[3][1] += a3 * k1; lg[3][2] += a3 * k2; lg[3][3] += a3 * k3;
        }
#pragma unroll
        for (int i = 0; i < 4; i++)
#pragma unroll
            for (int j = 0; j < 4; j++)
                Ls[rr + i][cc + j] =
                    fminf(fmaxf(lg[i][j], -50000.0f), 50000.0f) + madd[cc + j];
        __syncthreads();

        // online softmax: row r handled by 4 threads (g = lane&3)
        float cmax = -INFINITY;
#pragma unroll
        for (int c = 0; c < 16; c++) cmax = fmaxf(cmax, Ls[r][g * 16 + c]);
        cmax = fmaxf(cmax, __shfl_xor_sync(0xffffffffu, cmax, 1));
        cmax = fmaxf(cmax, __shfl_xor_sync(0xffffffffu, cmax, 2));
        float newm = fmaxf(m, cmax);
        float csum = 0.0f;
#pragma unroll
        for (int c = 0; c < 16; c++) {
            float p = __expf(Ls[r][g * 16 + c] - newm);
            Ls[r][g * 16 + c] = p;
            csum += p;
        }
        csum += __shfl_xor_sync(0xffffffffu, csum, 1);
        csum += __shfl_xor_sync(0xffffffffu, csum, 2);
        float factor = __expf(m - newm);   // exp(-inf)=0 on first chunk
        l = l * factor + csum;
#pragma unroll
        for (int d = 0; d < 8; d++) acc[d] *= factor;
        m = newm;
        __syncthreads();

        // PV: each thread owns 8 dims of its row
#pragma unroll
        for (int s = 0; s < AS; s++) {
            float p = Ls[r][s];
#pragma unroll
            for (int d = 0; d < 8; d++)
                acc[d] += p * Vs[s][g * 8 + d];
        }
        __syncthreads();
    }

    int t = t0 + r;
    if (t < TTOT) {
        float inv = 1.0f / l;
#pragma unroll
        for (int d = 0; d < 8; d++)
            Ob[((size_t)(b * TTOT + t)) * CH + h * HD + g * 8 + d] = acc[d] * inv;
    }
}

// ---------------- launch ------------------------------------------------------
extern "C" void kernel_launch(void* const* d_in, const int* in_sizes, int n_in,
                              void* d_out, int out_size)
{
    const float* qin[5];
    for (int i = 0; i < 5; i++) qin[i] = (const float*)d_in[i];
    const float* cache  = (const float*)d_in[5];
    const int*   mask   = (const int*)d_in[6];
    const float* ln_v_g = (const float*)d_in[7];
    const float* ln_v_b = (const float*)d_in[8];
    const float* ln_c_g = (const float*)d_in[9];
    const float* ln_c_b = (const float*)d_in[10];
    const float* Wv  = (const float*)d_in[11];
    const float* bv  = (const float*)d_in[12];
    const float* Wc  = (const float*)d_in[13];
    const float* bc  = (const float*)d_in[14];
    const float* Wvc = (const float*)d_in[15];
    const float* bvc = (const float*)d_in[16];
    const float* Wo  = (const float*)d_in[17];
    const float* bo  = (const float*)d_in[18];
    const float* Wg1 = (const float*)d_in[19];
    const float* bg1 = (const float*)d_in[20];
    const float* Wg2 = (const float*)d_in[21];
    const float* bg2 = (const float*)d_in[22];
    float* out = (float*)d_out;

    float *pv, *pvn, *pq, *pcn, *pk, *pval, *po, *pdelta, *pg1, *pnv;
    cudaGetSymbolAddress((void**)&pv,     g_v);
    cudaGetSymbolAddress((void**)&pvn,    g_vn);
    cudaGetSymbolAddress((void**)&pq,     g_q);
    cudaGetSymbolAddress((void**)&pcn,    g_cn);
    cudaGetSymbolAddress((void**)&pk,     g_k);
    cudaGetSymbolAddress((void**)&pval,   g_val);
    cudaGetSymbolAddress((void**)&po,     g_o);
    cudaGetSymbolAddress((void**)&pdelta, g_delta);
    cudaGetSymbolAddress((void**)&pg1,    g_g1);
    cudaGetSymbolAddress((void**)&pnv,    g_nv);

    static const int    hw[5] = {6400, 1600, 400, 100, 25};
    static const int    st[5] = {0, 6400, 8000, 8400, 8500};
    static const size_t ob[5] = {0, 3276800, 4096000, 4300800, 4352000};

    const int MROWS = BSZ * TTOT;               // 17050
    const int CROWS = BSZ * SCTX;               // 2048
    const float scale = 0.1767766952966369f;    // 32^-0.5

    dim3 tb(32, 8);
    for (int lv = 0; lv < 5; lv++) {
        dim3 grid((hw[lv] + 31) / 32, CH / 32, BSZ);
        gather_kernel<<<grid, tb>>>(qin[lv], pv, hw[lv], st[lv]);
    }

    ln_kernel<<<MROWS, 256>>>(pv, ln_v_g, ln_v_b, pvn);
    ln_kernel<<<CROWS, 256>>>(cache, ln_c_g, ln_c_b, pcn);

    dim3 gq(CH / GBN, (MROWS + GBM - 1) / GBM);   // (4, 267)
    dim3 gc(CH / GBN, CROWS / GBM);               // (4, 32)
    gemm_kernel<1><<<gq, 256>>>(pvn, Wv, bv, pq, MROWS, CH, CH, scale, nullptr, nullptr);
    gemm_kernel<0><<<gc, 256>>>(pcn, Wc,  bc,  pk,   CROWS, CH, CH, 1.0f, nullptr, nullptr);
    gemm_kernel<0><<<gc, 256>>>(pcn, Wvc, bvc, pval, CROWS, CH, CH, 1.0f, nullptr, nullptr);

    dim3 ga((TTOT + AQ - 1) / AQ, NH, BSZ);       // (134, 8, 2)
    attn_kernel<<<ga, 256>>>(pq, pk, pval, mask, po);

    gemm_kernel<0><<<gq, 256>>>(po, Wo, bo, pdelta, MROWS, CH, CH, 1.0f, nullptr, nullptr);

    dim3 gg1(CH / 2 / GBN, (MROWS + GBM - 1) / GBM);  // (2, 267)
    gemm_kernel<2><<<gg1, 256>>>(pv, Wg1, bg1, pg1, MROWS, CH / 2, CH, 1.0f, nullptr, nullptr);

    gemm_kernel<3><<<gq, 256>>>(pg1, Wg2, bg2, pnv, MROWS, CH, CH / 2, 1.0f, pv, pdelta);

    for (int lv = 0; lv < 5; lv++) {
        dim3 grid((hw[lv] + 31) / 32, CH / 32, BSZ);
        scatter_kernel<<<grid, tb>>>(pnv, out, hw[lv], st[lv], ob[lv]);
    }
}

// round 4
// speedup vs baseline: 2.3495x; 2.3495x over previous
#include <cuda_runtime.h>
#include <math.h>

#define BSZ   2
#define CH    256
#define SCTX  1024
#define NH    8
#define HD    32
#define TTOT  8525

// ---------------- scratch (__device__ globals; no runtime allocation) --------
__device__ float g_v    [BSZ * TTOT * CH];
__device__ float g_vn   [BSZ * TTOT * CH];
__device__ float g_q    [BSZ * TTOT * CH];
__device__ float g_cn   [BSZ * SCTX * CH];
__device__ float g_k    [BSZ * SCTX * CH];
__device__ float g_val  [BSZ * SCTX * CH];
__device__ float g_o    [BSZ * TTOT * CH];
__device__ float g_delta[BSZ * TTOT * CH];
__device__ float g_g1   [BSZ * TTOT * (CH / 2)];
__device__ float g_nv   [BSZ * TTOT * CH];
__device__ int   g_sidx [BSZ * SCTX];
__device__ int   g_scnt [BSZ];

// ---------------- gather: (b, c, hw) -> v (b, t, c), tiled transpose ---------
__global__ void gather_kernel(const float* __restrict__ in, float* __restrict__ v,
                              int hw, int tstart)
{
    __shared__ float tile[32][33];
    int b   = blockIdx.z;
    int ch0 = blockIdx.y * 32;
    int p0  = blockIdx.x * 32;
    int tx = threadIdx.x, ty = threadIdx.y;   // 32 x 8
#pragma unroll
    for (int i = 0; i < 4; i++) {
        int ch = ch0 + ty + i * 8;
        int p  = p0 + tx;
        if (p < hw)
            tile[ty + i * 8][tx] = in[((size_t)(b * CH + ch)) * hw + p];
    }
    __syncthreads();
#pragma unroll
    for (int i = 0; i < 4; i++) {
        int p  = p0 + ty + i * 8;
        int ch = ch0 + tx;
        if (p < hw)
            v[((size_t)(b * TTOT + tstart + p)) * CH + ch] = tile[tx][ty + i * 8];
    }
}

// ---------------- scatter: nv (b, t, c) -> out level block (b, c, hw) --------
__global__ void scatter_kernel(const float* __restrict__ nv, float* __restrict__ out,
                               int hw, int tstart, size_t obase)
{
    __shared__ float tile[32][33];
    int b   = blockIdx.z;
    int ch0 = blockIdx.y * 32;
    int p0  = blockIdx.x * 32;
    int tx = threadIdx.x, ty = threadIdx.y;
#pragma unroll
    for (int i = 0; i < 4; i++) {
        int p  = p0 + ty + i * 8;
        int ch = ch0 + tx;
        if (p < hw)
            tile[ty + i * 8][tx] = nv[((size_t)(b * TTOT + tstart + p)) * CH + ch];
    }
    __syncthreads();
#pragma unroll
    for (int i = 0; i < 4; i++) {
        int ch = ch0 + ty + i * 8;
        int p  = p0 + tx;
        if (p < hw)
            out[obase + ((size_t)(b * CH + ch)) * hw + p] = tile[tx][ty + i * 8];
    }
}

// ---------------- layernorm over last dim (256), one block per row -----------
__global__ void ln_kernel(const float* __restrict__ x, const float* __restrict__ gg,
                          const float* __restrict__ bb, float* __restrict__ y)
{
    int row = blockIdx.x;
    int tid = threadIdx.x;          // 256 threads
    float v = x[(size_t)row * CH + tid];
    float s = v, sq = v * v;
#pragma unroll
    for (int o = 16; o > 0; o >>= 1) {
        s  += __shfl_xor_sync(0xffffffffu, s,  o);
        sq += __shfl_xor_sync(0xffffffffu, sq, o);
    }
    __shared__ float ss[8], ssq[8];
    int w = tid >> 5, l = tid & 31;
    if (l == 0) { ss[w] = s; ssq[w] = sq; }
    __syncthreads();
    if (w == 0) {
        float s2 = ss[l & 7], q2 = ssq[l & 7];
#pragma unroll
        for (int o = 4; o > 0; o >>= 1) {
            s2 += __shfl_xor_sync(0xffffffffu, s2, o);
            q2 += __shfl_xor_sync(0xffffffffu, q2, o);
        }
        if (l == 0) { ss[0] = s2; ssq[0] = q2; }
    }
    __syncthreads();
    float mean = ss[0] * (1.0f / CH);
    float var  = ssq[0] * (1.0f / CH) - mean * mean;
    y[(size_t)row * CH + tid] = (v - mean) * rsqrtf(var + 1e-5f) * gg[tid] + bb[tid];
}

// ---------------- mask compaction: list of valid s per batch -----------------
__global__ void compact_kernel(const int* __restrict__ mask, int* __restrict__ sidx,
                               int* __restrict__ scnt)
{
    int b = blockIdx.x, t = threadIdx.x;         // 1024 threads
    __shared__ int wsum[32];
    int m = mask[b * SCTX + t];
    unsigned bal = __ballot_sync(0xffffffffu, m != 0);
    int lane = t & 31, w = t >> 5;
    if (lane == 0) wsum[w] = __popc(bal);
    __syncthreads();
    if (w == 0) {
        int v = wsum[lane];
#pragma unroll
        for (int o = 1; o < 32; o <<= 1) {
            int n = __shfl_up_sync(0xffffffffu, v, o);
            if (lane >= o) v += n;
        }
        wsum[lane] = v;                           // inclusive scan
    }
    __syncthreads();
    int base = (w == 0) ? 0 : wsum[w - 1];
    int pre  = __popc(bal & ((1u << lane) - 1u));
    if (m) sidx[b * SCTX + base + pre] = t;
    if (t == 0) scnt[b] = wsum[31];
}

// ---------------- generic GEMM: C = epi(A @ W + bias), 128x64 blocks ---------
// EPI 0: +bias   1: (+bias)*scale   2: relu(+bias)   3: vres + tanh(+bias)*dres
#define GBM 128
#define GBN 64
#define GBK 32

template <int EPI>
__global__ void __launch_bounds__(256)
gemm_kernel(const float* __restrict__ A, const float* __restrict__ W,
            const float* __restrict__ bias, float* __restrict__ Cm,
            int M, int N, int K, float scale,
            const float* __restrict__ vres, const float* __restrict__ dres)
{
    __shared__ __align__(16) float Ast[GBK][GBM + 4];   // transposed A: [k][row]
    __shared__ __align__(16) float Bs [GBK][GBN + 4];
    int bm  = blockIdx.y * GBM;
    int bn  = blockIdx.x * GBN;
    int tid = threadIdx.x;                 // 256
    int trow = tid >> 4;                   // 0..15 -> rows trow*8..+7
    int tcol = tid & 15;                   // 0..15 -> cols tcol*4..+3
    float acc[8][4] = {};
    for (int k0 = 0; k0 < K; k0 += GBK) {
        // A tile: 128x32 = 1024 float4, transpose into Ast
#pragma unroll
        for (int e = 0; e < 4; e++) {
            int lin = tid + e * 256;
            int r = lin >> 3, c4 = (lin & 7) << 2;
            int gr = bm + r;
            float4 av = make_float4(0.f, 0.f, 0.f, 0.f);
            if (gr < M) av = *(const float4*)&A[(size_t)gr * K + k0 + c4];
            Ast[c4 + 0][r] = av.x;
            Ast[c4 + 1][r] = av.y;
            Ast[c4 + 2][r] = av.z;
            Ast[c4 + 3][r] = av.w;
        }
        // B tile: 32x64 = 512 float4
#pragma unroll
        for (int e = 0; e < 2; e++) {
            int lin = tid + e * 256;
            int r = lin >> 4, c4 = (lin & 15) << 2;
            *(float4*)&Bs[r][c4] = *(const float4*)&W[(size_t)(k0 + r) * N + bn + c4];
        }
        __syncthreads();
#pragma unroll
        for (int k = 0; k < GBK; k++) {
            float4 aL = *(float4*)&Ast[k][trow * 8];
            float4 aH = *(float4*)&Ast[k][trow * 8 + 4];
            float4 bv = *(float4*)&Bs[k][tcol * 4];
            float a[8] = {aL.x, aL.y, aL.z, aL.w, aH.x, aH.y, aH.z, aH.w};
#pragma unroll
            for (int i = 0; i < 8; i++) {
                acc[i][0] += a[i] * bv.x;
                acc[i][1] += a[i] * bv.y;
                acc[i][2] += a[i] * bv.z;
                acc[i][3] += a[i] * bv.w;
            }
        }
        __syncthreads();
    }
    float4 bb = *(const float4*)&bias[bn + tcol * 4];
#pragma unroll
    for (int i = 0; i < 8; i++) {
        int gr = bm + trow * 8 + i;
        if (gr >= M) continue;
        float vv[4] = {acc[i][0] + bb.x, acc[i][1] + bb.y,
                       acc[i][2] + bb.z, acc[i][3] + bb.w};
#pragma unroll
        for (int j = 0; j < 4; j++) {
            int gc = bn + tcol * 4 + j;
            float val = vv[j];
            if (EPI == 1) val *= scale;
            if (EPI == 2) val = fmaxf(val, 0.0f);
            if (EPI == 3) {
                size_t ridx = (size_t)gr * 256 + gc;   // vres/dres have 256 cols
                val = vres[ridx] + tanhf(val) * dres[ridx];
            }
            vv[j] = val;
        }
        *(float4*)&Cm[(size_t)gr * N + bn + tcol * 4] =
            make_float4(vv[0], vv[1], vv[2], vv[3]);
    }
}

// ---------------- flash attention over compacted valid keys ------------------
#define AQ 128
#define AS 64
// dynamic smem layout (floats):
//   Qst [32][132]   off 0       (transposed Q:  [k][row])
//   Kst [32][68]    off 4224    (transposed K:  [k][s])
//   Vst [32][68]    off 6400    (transposed V:  [d][s])
//   Ls  [128][68]   off 8576    (logits / probs, row-major)
//   rowm[128] rowl[128] rowfac[128]  off 17280
#define ATTN_SMEM_FLOATS (17280 + 384)
#define ATTN_SMEM_BYTES  (ATTN_SMEM_FLOATS * 4)

__global__ void __launch_bounds__(256)
attn_kernel(const float* __restrict__ Qb, const float* __restrict__ Kb,
            const float* __restrict__ Vb, const int* __restrict__ sidxp,
            const int* __restrict__ scnt, float* __restrict__ Ob)
{
    extern __shared__ __align__(16) float sm[];
    float* Qst    = sm;            // stride 132
    float* Kst    = sm + 4224;     // stride 68
    float* Vst    = sm + 6400;     // stride 68
    float* Ls     = sm + 8576;     // stride 68
    float* rowm   = sm + 17280;
    float* rowl   = sm + 17408;
    float* rowfac = sm + 17536;

    int b  = blockIdx.z;
    int h  = blockIdx.y;
    int t0 = blockIdx.x * AQ;
    int tid = threadIdx.x;               // 256
    int trow = tid >> 4;                 // 0..15
    int tcol = tid & 15;                 // 0..15
    int cnt = scnt[b];

    if (tid < AQ) { rowm[tid] = -INFINITY; rowl[tid] = 0.0f; }

    // load Q tile transposed: [k][row]
#pragma unroll
    for (int e = 0; e < 4; e++) {
        int lin = tid + e * 256;
        int r = lin >> 3, c4 = (lin & 7) << 2;
        int t = t0 + r;
        float4 qv = make_float4(0.f, 0.f, 0.f, 0.f);
        if (t < TTOT) qv = *(const float4*)&Qb[((size_t)(b * TTOT + t)) * CH + h * HD + c4];
        Qst[(c4 + 0) * 132 + r] = qv.x;
        Qst[(c4 + 1) * 132 + r] = qv.y;
        Qst[(c4 + 2) * 132 + r] = qv.z;
        Qst[(c4 + 3) * 132 + r] = qv.w;
    }

    float acc[8][2] = {};

    for (int s0 = 0; s0 < cnt; s0 += AS) {
        int rem = cnt - s0;
        __syncthreads();   // protect Kst/Vst/Ls reuse + first-iter Q/init visibility

        // load K/V chunk (gathered via index list), transposed
#pragma unroll
        for (int e = 0; e < 2; e++) {
            int lin = tid + e * 256;
            int sr = lin >> 3, c4 = (lin & 7) << 2;
            int sidx = (sr < rem) ? sidxp[b * SCTX + s0 + sr] : 0;
            size_t gbase = ((size_t)(b * SCTX + sidx)) * CH + h * HD + c4;
            float4 kv = *(const float4*)&Kb[gbase];
            float4 vv = *(const float4*)&Vb[gbase];
            Kst[(c4 + 0) * 68 + sr] = kv.x;
            Kst[(c4 + 1) * 68 + sr] = kv.y;
            Kst[(c4 + 2) * 68 + sr] = kv.z;
            Kst[(c4 + 3) * 68 + sr] = kv.w;
            Vst[(c4 + 0) * 68 + sr] = vv.x;
            Vst[(c4 + 1) * 68 + sr] = vv.y;
            Vst[(c4 + 2) * 68 + sr] = vv.z;
            Vst[(c4 + 3) * 68 + sr] = vv.w;
        }
        __syncthreads();

        // logits: 8x4 micro-tile per thread
        float lg[8][4] = {};
#pragma unroll
        for (int k = 0; k < HD; k++) {
            float4 aL = *(float4*)&Qst[k * 132 + trow * 8];
            float4 aH = *(float4*)&Qst[k * 132 + trow * 8 + 4];
            float4 bv = *(float4*)&Kst[k * 68 + tcol * 4];
            float a[8] = {aL.x, aL.y, aL.z, aL.w, aH.x, aH.y, aH.z, aH.w};
#pragma unroll
            for (int i = 0; i < 8; i++) {
                lg[i][0] += a[i] * bv.x;
                lg[i][1] += a[i] * bv.y;
                lg[i][2] += a[i] * bv.z;
                lg[i][3] += a[i] * bv.w;
            }
        }
        float mj[4];
#pragma unroll
        for (int j = 0; j < 4; j++)
            mj[j] = (s0 + tcol * 4 + j < cnt) ? 1.0f : -9e15f;
#pragma unroll
        for (int i = 0; i < 8; i++) {
            float4 o;
            o.x = fminf(fmaxf(lg[i][0], -50000.0f), 50000.0f) + mj[0];
            o.y = fminf(fmaxf(lg[i][1], -50000.0f), 50000.0f) + mj[1];
            o.z = fminf(fmaxf(lg[i][2], -50000.0f), 50000.0f) + mj[2];
            o.w = fminf(fmaxf(lg[i][3], -50000.0f), 50000.0f) + mj[3];
            *(float4*)&Ls[(trow * 8 + i) * 68 + tcol * 4] = o;
        }
        __syncthreads();

        // online softmax: 2 threads per row (tid>>1 = row, tid&1 = half)
        {
            int r = tid >> 1, half = tid & 1;
            float* lrow = Ls + r * 68 + half * 32;
            float v[32];
#pragma unroll
            for (int q = 0; q < 8; q++) {
                float4 t4 = *(float4*)(lrow + q * 4);
                v[q * 4 + 0] = t4.x; v[q * 4 + 1] = t4.y;
                v[q * 4 + 2] = t4.z; v[q * 4 + 3] = t4.w;
            }
            float mold = rowm[r];
            float cmax = -INFINITY;
#pragma unroll
            for (int j = 0; j < 32; j++) cmax = fmaxf(cmax, v[j]);
            cmax = fmaxf(cmax, __shfl_xor_sync(0xffffffffu, cmax, 1));
            float newm = fmaxf(mold, cmax);
            float csum = 0.0f;
#pragma unroll
            for (int j = 0; j < 32; j++) {
                v[j] = __expf(v[j] - newm);
                csum += v[j];
            }
#pragma unroll
            for (int q = 0; q < 8; q++)
                *(float4*)(lrow + q * 4) =
                    make_float4(v[q * 4], v[q * 4 + 1], v[q * 4 + 2], v[q * 4 + 3]);
            csum += __shfl_xor_sync(0xffffffffu, csum, 1);
            float fac = __expf(mold - newm);
            if (half == 0) {
                rowfac[r] = fac;
                rowl[r]   = rowl[r] * fac + csum;
                rowm[r]   = newm;
            }
        }
        __syncthreads();

        // PV: 8 rows x 2 dims per thread, s tiled by 4
        {
            float fi[8];
#pragma unroll
            for (int i = 0; i < 8; i++) fi[i] = rowfac[trow * 8 + i];
#pragma unroll
            for (int i = 0; i < 8; i++) {
                acc[i][0] *= fi[i];
                acc[i][1] *= fi[i];
            }
#pragma unroll
            for (int s4 = 0; s4 < AS / 4; s4++) {
                float4 va = *(float4*)&Vst[(tcol * 2 + 0) * 68 + s4 * 4];
                float4 vb = *(float4*)&Vst[(tcol * 2 + 1) * 68 + s4 * 4];
#pragma unroll
                for (int i = 0; i < 8; i++) {
                    float4 p = *(float4*)&Ls[(trow * 8 + i) * 68 + s4 * 4];
                    acc[i][0] += p.x * va.x + p.y * va.y + p.z * va.z + p.w * va.w;
                    acc[i][1] += p.x * vb.x + p.y * vb.y + p.z * vb.z + p.w * vb.w;
                }
            }
        }
    }

#pragma unroll
    for (int i = 0; i < 8; i++) {
        int t = t0 + trow * 8 + i;
        if (t < TTOT) {
            float inv = 1.0f / rowl[trow * 8 + i];
            float2 o2 = make_float2(acc[i][0] * inv, acc[i][1] * inv);
            *(float2*)&Ob[((size_t)(b * TTOT + t)) * CH + h * HD + tcol * 2] = o2;
        }
    }
}

// ---------------- launch ------------------------------------------------------
extern "C" void kernel_launch(void* const* d_in, const int* in_sizes, int n_in,
                              void* d_out, int out_size)
{
    const float* qin[5];
    for (int i = 0; i < 5; i++) qin[i] = (const float*)d_in[i];
    const float* cache  = (const float*)d_in[5];
    const int*   mask   = (const int*)d_in[6];
    const float* ln_v_g = (const float*)d_in[7];
    const float* ln_v_b = (const float*)d_in[8];
    const float* ln_c_g = (const float*)d_in[9];
    const float* ln_c_b = (const float*)d_in[10];
    const float* Wv  = (const float*)d_in[11];
    const float* bv  = (const float*)d_in[12];
    const float* Wc  = (const float*)d_in[13];
    const float* bc  = (const float*)d_in[14];
    const float* Wvc = (const float*)d_in[15];
    const float* bvc = (const float*)d_in[16];
    const float* Wo  = (const float*)d_in[17];
    const float* bo  = (const float*)d_in[18];
    const float* Wg1 = (const float*)d_in[19];
    const float* bg1 = (const float*)d_in[20];
    const float* Wg2 = (const float*)d_in[21];
    const float* bg2 = (const float*)d_in[22];
    float* out = (float*)d_out;

    float *pv, *pvn, *pq, *pcn, *pk, *pval, *po, *pdelta, *pg1, *pnv;
    int *psidx, *pscnt;
    cudaGetSymbolAddress((void**)&pv,     g_v);
    cudaGetSymbolAddress((void**)&pvn,    g_vn);
    cudaGetSymbolAddress((void**)&pq,     g_q);
    cudaGetSymbolAddress((void**)&pcn,    g_cn);
    cudaGetSymbolAddress((void**)&pk,     g_k);
    cudaGetSymbolAddress((void**)&pval,   g_val);
    cudaGetSymbolAddress((void**)&po,     g_o);
    cudaGetSymbolAddress((void**)&pdelta, g_delta);
    cudaGetSymbolAddress((void**)&pg1,    g_g1);
    cudaGetSymbolAddress((void**)&pnv,    g_nv);
    cudaGetSymbolAddress((void**)&psidx,  g_sidx);
    cudaGetSymbolAddress((void**)&pscnt,  g_scnt);

    cudaFuncSetAttribute(attn_kernel,
                         cudaFuncAttributeMaxDynamicSharedMemorySize, ATTN_SMEM_BYTES);

    static const int    hw[5] = {6400, 1600, 400, 100, 25};
    static const int    st[5] = {0, 6400, 8000, 8400, 8500};
    static const size_t ob[5] = {0, 3276800, 4096000, 4300800, 4352000};

    const int MROWS = BSZ * TTOT;               // 17050
    const int CROWS = BSZ * SCTX;               // 2048
    const float scale = 0.1767766952966369f;    // 32^-0.5

    dim3 tb(32, 8);
    for (int lv = 0; lv < 5; lv++) {
        dim3 grid((hw[lv] + 31) / 32, CH / 32, BSZ);
        gather_kernel<<<grid, tb>>>(qin[lv], pv, hw[lv], st[lv]);
    }

    compact_kernel<<<BSZ, 1024>>>(mask, psidx, pscnt);

    ln_kernel<<<MROWS, 256>>>(pv, ln_v_g, ln_v_b, pvn);
    ln_kernel<<<CROWS, 256>>>(cache, ln_c_g, ln_c_b, pcn);

    dim3 gq(CH / GBN, (MROWS + GBM - 1) / GBM);   // (4, 134)
    dim3 gc(CH / GBN, CROWS / GBM);               // (4, 16)
    gemm_kernel<1><<<gq, 256>>>(pvn, Wv, bv, pq, MROWS, CH, CH, scale, nullptr, nullptr);
    gemm_kernel<0><<<gc, 256>>>(pcn, Wc,  bc,  pk,   CROWS, CH, CH, 1.0f, nullptr, nullptr);
    gemm_kernel<0><<<gc, 256>>>(pcn, Wvc, bvc, pval, CROWS, CH, CH, 1.0f, nullptr, nullptr);

    dim3 ga((TTOT + AQ - 1) / AQ, NH, BSZ);       // (67, 8, 2)
    attn_kernel<<<ga, 256, ATTN_SMEM_BYTES>>>(pq, pk, pval, psidx, pscnt, po);

    gemm_kernel<0><<<gq, 256>>>(po, Wo, bo, pdelta, MROWS, CH, CH, 1.0f, nullptr, nullptr);

    dim3 gg1(CH / 2 / GBN, (MROWS + GBM - 1) / GBM);  // (1, 134)
    gemm_kernel<2><<<gg1, 256>>>(pv, Wg1, bg1, pg1, MROWS, CH / 2, CH, 1.0f, nullptr, nullptr);

    gemm_kernel<3><<<gq, 256>>>(pg1, Wg2, bg2, pnv, MROWS, CH, CH / 2, 1.0f, pv, pdelta);

    for (int lv = 0; lv < 5; lv++) {
        dim3 grid((hw[lv] + 31) / 32, CH / 32, BSZ);
        scatter_kernel<<<grid, tb>>>(pnv, out, hw[lv], st[lv], ob[lv]);
    }
}

// round 8
// speedup vs baseline: 2.4716x; 1.0520x over previous
#include <cuda_runtime.h>
#include <math.h>

#define BSZ   2
#define CH    256
#define SCTX  1024
#define NH    8
#define HD    32
#define TTOT  8525

typedef unsigned long long ull;

// ---- f32x2 packed math helpers (Blackwell FFMA2 path) ------------------------
__device__ __forceinline__ void fma2(ull& d, ull a, ull b) {
    asm("fma.rn.f32x2 %0, %1, %2, %0;" : "+l"(d) : "l"(a), "l"(b));
}
__device__ __forceinline__ void mul2(ull& d, ull a) {
    asm("mul.rn.f32x2 %0, %0, %1;" : "+l"(d) : "l"(a));
}
__device__ __forceinline__ ull bcast2(float f) {
    ull d; unsigned u = __float_as_uint(f);
    asm("mov.b64 %0, {%1, %1};" : "=l"(d) : "r"(u));
    return d;
}
__device__ __forceinline__ ull pack2(float lo, float hi) {
    ull d; unsigned a = __float_as_uint(lo), b = __float_as_uint(hi);
    asm("mov.b64 %0, {%1, %2};" : "=l"(d) : "r"(a), "r"(b));
    return d;
}
__device__ __forceinline__ float2 unpack2(ull v) {
    unsigned lo, hi;
    asm("mov.b64 {%0, %1}, %2;" : "=r"(lo), "=r"(hi) : "l"(v));
    return make_float2(__uint_as_float(lo), __uint_as_float(hi));
}

// ---------------- scratch (__device__ globals; no runtime allocation) --------
__device__ float g_v    [BSZ * TTOT * CH];
__device__ float g_vn   [BSZ * TTOT * CH];
__device__ float g_q    [BSZ * TTOT * CH];
__device__ float g_cn   [BSZ * SCTX * CH];
__device__ float g_k    [BSZ * SCTX * CH];
__device__ float g_val  [BSZ * SCTX * CH];
__device__ float g_o    [BSZ * TTOT * CH];
__device__ float g_delta[BSZ * TTOT * CH];
__device__ float g_g1   [BSZ * TTOT * (CH / 2)];
__device__ float g_nv   [BSZ * TTOT * CH];
__device__ int   g_sidx [BSZ * SCTX];
__device__ int   g_scnt [BSZ];

// ---------------- gather: (b, c, hw) -> v (b, t, c), tiled transpose ---------
__global__ void gather_kernel(const float* __restrict__ in, float* __restrict__ v,
                              int hw, int tstart)
{
    __shared__ float tile[32][33];
    int b   = blockIdx.z;
    int ch0 = blockIdx.y * 32;
    int p0  = blockIdx.x * 32;
    int tx = threadIdx.x, ty = threadIdx.y;   // 32 x 8
#pragma unroll
    for (int i = 0; i < 4; i++) {
        int ch = ch0 + ty + i * 8;
        int p  = p0 + tx;
        if (p < hw)
            tile[ty + i * 8][tx] = in[((size_t)(b * CH + ch)) * hw + p];
    }
    __syncthreads();
#pragma unroll
    for (int i = 0; i < 4; i++) {
        int p  = p0 + ty + i * 8;
        int ch = ch0 + tx;
        if (p < hw)
            v[((size_t)(b * TTOT + tstart + p)) * CH + ch] = tile[tx][ty + i * 8];
    }
}

// ---------------- scatter: nv (b, t, c) -> out level block (b, c, hw) --------
__global__ void scatter_kernel(const float* __restrict__ nv, float* __restrict__ out,
                               int hw, int tstart, size_t obase)
{
    __shared__ float tile[32][33];
    int b   = blockIdx.z;
    int ch0 = blockIdx.y * 32;
    int p0  = blockIdx.x * 32;
    int tx = threadIdx.x, ty = threadIdx.y;
#pragma unroll
    for (int i = 0; i < 4; i++) {
        int p  = p0 + ty + i * 8;
        int ch = ch0 + tx;
        if (p < hw)
            tile[ty + i * 8][tx] = nv[((size_t)(b * TTOT + tstart + p)) * CH + ch];
    }
    __syncthreads();
#pragma unroll
    for (int i = 0; i < 4; i++) {
        int ch = ch0 + ty + i * 8;
        int p  = p0 + tx;
        if (p < hw)
            out[obase + ((size_t)(b * CH + ch)) * hw + p] = tile[tx][ty + i * 8];
    }
}

// ---------------- layernorm over last dim (256), one block per row -----------
__global__ void ln_kernel(const float* __restrict__ x, const float* __restrict__ gg,
                          const float* __restrict__ bb, float* __restrict__ y)
{
    int row = blockIdx.x;
    int tid = threadIdx.x;          // 256 threads
    float v = x[(size_t)row * CH + tid];
    float s = v, sq = v * v;
#pragma unroll
    for (int o = 16; o > 0; o >>= 1) {
        s  += __shfl_xor_sync(0xffffffffu, s,  o);
        sq += __shfl_xor_sync(0xffffffffu, sq, o);
    }
    __shared__ float ss[8], ssq[8];
    int w = tid >> 5, l = tid & 31;
    if (l == 0) { ss[w] = s; ssq[w] = sq; }
    __syncthreads();
    if (w == 0) {
        float s2 = ss[l & 7], q2 = ssq[l & 7];
#pragma unroll
        for (int o = 4; o > 0; o >>= 1) {
            s2 += __shfl_xor_sync(0xffffffffu, s2, o);
            q2 += __shfl_xor_sync(0xffffffffu, q2, o);
        }
        if (l == 0) { ss[0] = s2; ssq[0] = q2; }
    }
    __syncthreads();
    float mean = ss[0] * (1.0f / CH);
    float var  = ssq[0] * (1.0f / CH) - mean * mean;
    y[(size_t)row * CH + tid] = (v - mean) * rsqrtf(var + 1e-5f) * gg[tid] + bb[tid];
}

// ---------------- mask compaction: list of valid s per batch -----------------
__global__ void compact_kernel(const int* __restrict__ mask, int* __restrict__ sidx,
                               int* __restrict__ scnt)
{
    int b = blockIdx.x, t = threadIdx.x;         // 1024 threads
    __shared__ int wsum[32];
    int m = mask[b * SCTX + t];
    unsigned bal = __ballot_sync(0xffffffffu, m != 0);
    int lane = t & 31, w = t >> 5;
    if (lane == 0) wsum[w] = __popc(bal);
    __syncthreads();
    if (w == 0) {
        int v = wsum[lane];
#pragma unroll
        for (int o = 1; o < 32; o <<= 1) {
            int n = __shfl_up_sync(0xffffffffu, v, o);
            if (lane >= o) v += n;
        }
        wsum[lane] = v;                           // inclusive scan
    }
    __syncthreads();
    int base = (w == 0) ? 0 : wsum[w - 1];
    int pre  = __popc(bal & ((1u << lane) - 1u));
    if (m) sidx[b * SCTX + base + pre] = t;
    if (t == 0) scnt[b] = wsum[31];
}

// ---------------- generic GEMM: C = epi(A @ W + bias), 128x64, FFMA2 ---------
// EPI 0: +bias   1: (+bias)*scale   2: relu(+bias)   3: vres + tanh(+bias)*dres
#define GBM 128
#define GBN 64
#define GBK 32

template <int EPI>
__global__ void __launch_bounds__(256)
gemm_kernel(const float* __restrict__ A, const float* __restrict__ W,
            const float* __restrict__ bias, float* __restrict__ Cm,
            int M, int N, int K, float scale,
            const float* __restrict__ vres, const float* __restrict__ dres)
{
    __shared__ __align__(16) float Ast[GBK][GBM + 4];   // transposed A: [k][row]
    __shared__ __align__(16) float Bs [GBK][GBN + 4];
    int bm  = blockIdx.y * GBM;
    int bn  = blockIdx.x * GBN;
    int tid = threadIdx.x;                 // 256
    int trow = tid >> 4;                   // 0..15 -> rows trow*8..+7
    int tcol = tid & 15;                   // 0..15 -> cols tcol*4..+3
    ull acc2[4][4] = {};                   // row-pair x col, packed f32x2
    for (int k0 = 0; k0 < K; k0 += GBK) {
#pragma unroll
        for (int e = 0; e < 4; e++) {
            int lin = tid + e * 256;
            int r = lin >> 3, c4 = (lin & 7) << 2;
            int gr = bm + r;
            float4 av = make_float4(0.f, 0.f, 0.f, 0.f);
            if (gr < M) av = *(const float4*)&A[(size_t)gr * K + k0 + c4];
            Ast[c4 + 0][r] = av.x;
            Ast[c4 + 1][r] = av.y;
            Ast[c4 + 2][r] = av.z;
            Ast[c4 + 3][r] = av.w;
        }
#pragma unroll
        for (int e = 0; e < 2; e++) {
            int lin = tid + e * 256;
            int r = lin >> 4, c4 = (lin & 15) << 2;
            *(float4*)&Bs[r][c4] = *(const float4*)&W[(size_t)(k0 + r) * N + bn + c4];
        }
        __syncthreads();
#pragma unroll
        for (int k = 0; k < GBK; k++) {
            ulonglong2 aL = *(const ulonglong2*)&Ast[k][trow * 8];      // rows (0,1)(2,3)
            ulonglong2 aH = *(const ulonglong2*)&Ast[k][trow * 8 + 4];  // rows (4,5)(6,7)
            float4 bv = *(const float4*)&Bs[k][tcol * 4];
            ull b0 = bcast2(bv.x), b1 = bcast2(bv.y);
            ull b2 = bcast2(bv.z), b3 = bcast2(bv.w);
            fma2(acc2[0][0], aL.x, b0); fma2(acc2[0][1], aL.x, b1);
            fma2(acc2[0][2], aL.x, b2); fma2(acc2[0][3], aL.x, b3);
            fma2(acc2[1][0], aL.y, b0); fma2(acc2[1][1], aL.y, b1);
            fma2(acc2[1][2], aL.y, b2); fma2(acc2[1][3], aL.y, b3);
            fma2(acc2[2][0], aH.x, b0); fma2(acc2[2][1], aH.x, b1);
            fma2(acc2[2][2], aH.x, b2); fma2(acc2[2][3], aH.x, b3);
            fma2(acc2[3][0], aH.y, b0); fma2(acc2[3][1], aH.y, b1);
            fma2(acc2[3][2], aH.y, b2); fma2(acc2[3][3], aH.y, b3);
        }
        __syncthreads();
    }
    float4 bb = *(const float4*)&bias[bn + tcol * 4];
#pragma unroll
    for (int rp = 0; rp < 4; rp++) {
        float2 c0 = unpack2(acc2[rp][0]);
        float2 c1 = unpack2(acc2[rp][1]);
        float2 c2 = unpack2(acc2[rp][2]);
        float2 c3 = unpack2(acc2[rp][3]);
        float rowv[2][4] = {{c0.x, c1.x, c2.x, c3.x},
                            {c0.y, c1.y, c2.y, c3.y}};
#pragma unroll
        for (int hh = 0; hh < 2; hh++) {
            int gr = bm + trow * 8 + rp * 2 + hh;
            if (gr >= M) continue;
            float vv[4] = {rowv[hh][0] + bb.x, rowv[hh][1] + bb.y,
                           rowv[hh][2] + bb.z, rowv[hh][3] + bb.w};
#pragma unroll
            for (int j = 0; j < 4; j++) {
                int gc = bn + tcol * 4 + j;
                float val = vv[j];
                if (EPI == 1) val *= scale;
                if (EPI == 2) val = fmaxf(val, 0.0f);
                if (EPI == 3) {
                    size_t ridx = (size_t)gr * 256 + gc;   // vres/dres have 256 cols
                    val = vres[ridx] + tanhf(val) * dres[ridx];
                }
                vv[j] = val;
            }
            *(float4*)&Cm[(size_t)gr * N + bn + tcol * 4] =
                make_float4(vv[0], vv[1], vv[2], vv[3]);
        }
    }
}

// ---------------- flash attention over compacted valid keys, FFMA2 -----------
#define AQ 128
#define AS 64
// dynamic smem layout (floats):
//   Qst [32][132]   off 0       (transposed Q: [k][row])
//   Kst [32][68]    off 4224    (transposed K: [k][s])
//   Vs  [64][36]    off 6400    (V row-major:  [s][d])
//   Lst [64][132]   off 8704    (logits/probs TRANSPOSED: [s][row])
//   rowm[128] off 17152  rowl[128] off 17280  rowfac[128] off 17408
#define ATTN_SMEM_FLOATS 17536
#define ATTN_SMEM_BYTES  (ATTN_SMEM_FLOATS * 4)

__global__ void __launch_bounds__(256)
attn_kernel(const float* __restrict__ Qb, const float* __restrict__ Kb,
            const float* __restrict__ Vb, const int* __restrict__ sidxp,
            const int* __restrict__ scnt, float* __restrict__ Ob)
{
    extern __shared__ __align__(16) float sm[];
    float* Qst    = sm;            // stride 132
    float* Kst    = sm + 4224;     // stride 68
    float* Vs     = sm + 6400;     // stride 36
    float* Lst    = sm + 8704;     // stride 132, [s][row]
    float* rowm   = sm + 17152;
    float* rowl   = sm + 17280;
    float* rowfac = sm + 17408;

    int b  = blockIdx.z;
    int h  = blockIdx.y;
    int t0 = blockIdx.x * AQ;
    int tid = threadIdx.x;               // 256
    int trow = tid >> 4;                 // 0..15
    int tcol = tid & 15;                 // 0..15
    int cnt = scnt[b];

    if (tid < AQ) { rowm[tid] = -INFINITY; rowl[tid] = 0.0f; }

    // load Q tile transposed: [k][row]
#pragma unroll
    for (int e = 0; e < 4; e++) {
        int lin = tid + e * 256;
        int r = lin >> 3, c4 = (lin & 7) << 2;
        int t = t0 + r;
        float4 qv = make_float4(0.f, 0.f, 0.f, 0.f);
        if (t < TTOT) qv = *(const float4*)&Qb[((size_t)(b * TTOT + t)) * CH + h * HD + c4];
        Qst[(c4 + 0) * 132 + r] = qv.x;
        Qst[(c4 + 1) * 132 + r] = qv.y;
        Qst[(c4 + 2) * 132 + r] = qv.z;
        Qst[(c4 + 3) * 132 + r] = qv.w;
    }

    ull acc2[4][2] = {};   // row-pair x dim, packed over rows

    for (int s0 = 0; s0 < cnt; s0 += AS) {
        int rem = cnt - s0;
        __syncthreads();   // protect Kst/Vs/Lst reuse + first-iter Q/init visibility

        // load K (transposed) / V (row-major) chunk via index list
#pragma unroll
        for (int e = 0; e < 2; e++) {
            int lin = tid + e * 256;
            int sr = lin >> 3, c4 = (lin & 7) << 2;
            int sidx = (sr < rem) ? sidxp[b * SCTX + s0 + sr] : 0;
            size_t gbase = ((size_t)(b * SCTX + sidx)) * CH + h * HD + c4;
            float4 kv = *(const float4*)&Kb[gbase];
            float4 vv = *(const float4*)&Vb[gbase];
            Kst[(c4 + 0) * 68 + sr] = kv.x;
            Kst[(c4 + 1) * 68 + sr] = kv.y;
            Kst[(c4 + 2) * 68 + sr] = kv.z;
            Kst[(c4 + 3) * 68 + sr] = kv.w;
            *(float4*)&Vs[sr * 36 + c4] = vv;
        }
        __syncthreads();

        // logits: 8x4 micro-tile per thread, packed row pairs
        ull lg2[4][4] = {};
#pragma unroll
        for (int k = 0; k < HD; k++) {
            ulonglong2 aL = *(const ulonglong2*)&Qst[k * 132 + trow * 8];
            ulonglong2 aH = *(const ulonglong2*)&Qst[k * 132 + trow * 8 + 4];
            float4 kv = *(const float4*)&Kst[k * 68 + tcol * 4];
            ull b0 = bcast2(kv.x), b1 = bcast2(kv.y);
            ull b2 = bcast2(kv.z), b3 = bcast2(kv.w);
            fma2(lg2[0][0], aL.x, b0); fma2(lg2[0][1], aL.x, b1);
            fma2(lg2[0][2], aL.x, b2); fma2(lg2[0][3], aL.x, b3);
            fma2(lg2[1][0], aL.y, b0); fma2(lg2[1][1], aL.y, b1);
            fma2(lg2[1][2], aL.y, b2); fma2(lg2[1][3], aL.y, b3);
            fma2(lg2[2][0], aH.x, b0); fma2(lg2[2][1], aH.x, b1);
            fma2(lg2[2][2], aH.x, b2); fma2(lg2[2][3], aH.x, b3);
            fma2(lg2[3][0], aH.y, b0); fma2(lg2[3][1], aH.y, b1);
            fma2(lg2[3][2], aH.y, b2); fma2(lg2[3][3], aH.y, b3);
        }
        // clip + mask, store TRANSPOSED: Lst[s][row]
#pragma unroll
        for (int j = 0; j < 4; j++) {
            float mj = (s0 + tcol * 4 + j < cnt) ? 1.0f : -9e15f;
            ulonglong2 stL, stH;
            {
                float2 c = unpack2(lg2[0][j]);
                c.x = fminf(fmaxf(c.x, -50000.0f), 50000.0f) + mj;
                c.y = fminf(fmaxf(c.y, -50000.0f), 50000.0f) + mj;
                stL.x = pack2(c.x, c.y);
            }
            {
                float2 c = unpack2(lg2[1][j]);
                c.x = fminf(fmaxf(c.x, -50000.0f), 50000.0f) + mj;
                c.y = fminf(fmaxf(c.y, -50000.0f), 50000.0f) + mj;
                stL.y = pack2(c.x, c.y);
            }
            {
                float2 c = unpack2(lg2[2][j]);
                c.x = fminf(fmaxf(c.x, -50000.0f), 50000.0f) + mj;
                c.y = fminf(fmaxf(c.y, -50000.0f), 50000.0f) + mj;
                stH.x = pack2(c.x, c.y);
            }
            {
                float2 c = unpack2(lg2[3][j]);
                c.x = fminf(fmaxf(c.x, -50000.0f), 50000.0f) + mj;
                c.y = fminf(fmaxf(c.y, -50000.0f), 50000.0f) + mj;
                stH.y = pack2(c.x, c.y);
            }
            int sIdx = tcol * 4 + j;
            *(ulonglong2*)&Lst[sIdx * 132 + trow * 8]     = stL;
            *(ulonglong2*)&Lst[sIdx * 132 + trow * 8 + 4] = stH;
        }
        __syncthreads();

        // online softmax over transposed Lst: 2 threads per row
        {
            int r = tid >> 1, half = tid & 1;
            float v[32];
#pragma unroll
            for (int q = 0; q < 32; q++)
                v[q] = Lst[(half * 32 + q) * 132 + r];
            float mold = rowm[r];
            float cmax = -INFINITY;
#pragma unroll
            for (int j = 0; j < 32; j++) cmax = fmaxf(cmax, v[j]);
            cmax = fmaxf(cmax, __shfl_xor_sync(0xffffffffu, cmax, 1));
            float newm = fmaxf(mold, cmax);
            float csum = 0.0f;
#pragma unroll
            for (int j = 0; j < 32; j++) {
                v[j] = __expf(v[j] - newm);
                csum += v[j];
            }
#pragma unroll
            for (int q = 0; q < 32; q++)
                Lst[(half * 32 + q) * 132 + r] = v[q];
            csum += __shfl_xor_sync(0xffffffffu, csum, 1);
            float fac = __expf(mold - newm);
            if (half == 0) {
                rowfac[r] = fac;
                rowl[r]   = rowl[r] * fac + csum;
                rowm[r]   = newm;
            }
        }
        __syncthreads();

        // PV: packed row-pairs, dims d0=tcol*2, d1=tcol*2+1
        {
#pragma unroll
            for (int rp = 0; rp < 4; rp++) {
                ull fpair = *(const ull*)&rowfac[trow * 8 + rp * 2];
                mul2(acc2[rp][0], fpair);
                mul2(acc2[rp][1], fpair);
            }
#pragma unroll 8
            for (int s = 0; s < AS; s++) {
                ulonglong2 pL = *(const ulonglong2*)&Lst[s * 132 + trow * 8];
                ulonglong2 pH = *(const ulonglong2*)&Lst[s * 132 + trow * 8 + 4];
                float2 v2 = *(const float2*)&Vs[s * 36 + tcol * 2];
                ull vb0 = bcast2(v2.x), vb1 = bcast2(v2.y);
                fma2(acc2[0][0], pL.x, vb0); fma2(acc2[0][1], pL.x, vb1);
                fma2(acc2[1][0], pL.y, vb0); fma2(acc2[1][1], pL.y, vb1);
                fma2(acc2[2][0], pH.x, vb0); fma2(acc2[2][1], pH.x, vb1);
                fma2(acc2[3][0], pH.y, vb0); fma2(acc2[3][1], pH.y, vb1);
            }
        }
    }

#pragma unroll
    for (int rp = 0; rp < 4; rp++) {
        float2 d0 = unpack2(acc2[rp][0]);   // dim d0: rows (2rp, 2rp+1)
        float2 d1 = unpack2(acc2[rp][1]);
        int rowA = trow * 8 + rp * 2;
        int tA = t0 + rowA, tB = tA + 1;
        if (tA < TTOT) {
            float inv = 1.0f / rowl[rowA];
            *(float2*)&Ob[((size_t)(b * TTOT + tA)) * CH + h * HD + tcol * 2] =
                make_float2(d0.x * inv, d1.x * inv);
        }
        if (tB < TTOT) {
            float inv = 1.0f / rowl[rowA + 1];
            *(float2*)&Ob[((size_t)(b * TTOT + tB)) * CH + h * HD + tcol * 2] =
                make_float2(d0.y * inv, d1.y * inv);
        }
    }
}

// ---------------- launch ------------------------------------------------------
extern "C" void kernel_launch(void* const* d_in, const int* in_sizes, int n_in,
                              void* d_out, int out_size)
{
    const float* qin[5];
    for (int i = 0; i < 5; i++) qin[i] = (const float*)d_in[i];
    const float* cache  = (const float*)d_in[5];
    const int*   mask   = (const int*)d_in[6];
    const float* ln_v_g = (const float*)d_in[7];
    const float* ln_v_b = (const float*)d_in[8];
    const float* ln_c_g = (const float*)d_in[9];
    const float* ln_c_b = (const float*)d_in[10];
    const float* Wv  = (const float*)d_in[11];
    const float* bv  = (const float*)d_in[12];
    const float* Wc  = (const float*)d_in[13];
    const float* bc  = (const float*)d_in[14];
    const float* Wvc = (const float*)d_in[15];
    const float* bvc = (const float*)d_in[16];
    const float* Wo  = (const float*)d_in[17];
    const float* bo  = (const float*)d_in[18];
    const float* Wg1 = (const float*)d_in[19];
    const float* bg1 = (const float*)d_in[20];
    const float* Wg2 = (const float*)d_in[21];
    const float* bg2 = (const float*)d_in[22];
    float* out = (float*)d_out;

    float *pv, *pvn, *pq, *pcn, *pk, *pval, *po, *pdelta, *pg1, *pnv;
    int *psidx, *pscnt;
    cudaGetSymbolAddress((void**)&pv,     g_v);
    cudaGetSymbolAddress((void**)&pvn,    g_vn);
    cudaGetSymbolAddress((void**)&pq,     g_q);
    cudaGetSymbolAddress((void**)&pcn,    g_cn);
    cudaGetSymbolAddress((void**)&pk,     g_k);
    cudaGetSymbolAddress((void**)&pval,   g_val);
    cudaGetSymbolAddress((void**)&po,     g_o);
    cudaGetSymbolAddress((void**)&pdelta, g_delta);
    cudaGetSymbolAddress((void**)&pg1,    g_g1);
    cudaGetSymbolAddress((void**)&pnv,    g_nv);
    cudaGetSymbolAddress((void**)&psidx,  g_sidx);
    cudaGetSymbolAddress((void**)&pscnt,  g_scnt);

    cudaFuncSetAttribute(attn_kernel,
                         cudaFuncAttributeMaxDynamicSharedMemorySize, ATTN_SMEM_BYTES);

    static const int    hw[5] = {6400, 1600, 400, 100, 25};
    static const int    st[5] = {0, 6400, 8000, 8400, 8500};
    static const size_t ob[5] = {0, 3276800, 4096000, 4300800, 4352000};

    const int MROWS = BSZ * TTOT;               // 17050
    const int CROWS = BSZ * SCTX;               // 2048
    const float scale = 0.1767766952966369f;    // 32^-0.5

    dim3 tb(32, 8);
    for (int lv = 0; lv < 5; lv++) {
        dim3 grid((hw[lv] + 31) / 32, CH / 32, BSZ);
        gather_kernel<<<grid, tb>>>(qin[lv], pv, hw[lv], st[lv]);
    }

    compact_kernel<<<BSZ, 1024>>>(mask, psidx, pscnt);

    ln_kernel<<<MROWS, 256>>>(pv, ln_v_g, ln_v_b, pvn);
    ln_kernel<<<CROWS, 256>>>(cache, ln_c_g, ln_c_b, pcn);

    dim3 gq(CH / GBN, (MROWS + GBM - 1) / GBM);   // (4, 134)
    dim3 gc(CH / GBN, CROWS / GBM);               // (4, 16)
    gemm_kernel<1><<<gq, 256>>>(pvn, Wv, bv, pq, MROWS, CH, CH, scale, nullptr, nullptr);
    gemm_kernel<0><<<gc, 256>>>(pcn, Wc,  bc,  pk,   CROWS, CH, CH, 1.0f, nullptr, nullptr);
    gemm_kernel<0><<<gc, 256>>>(pcn, Wvc, bvc, pval, CROWS, CH, CH, 1.0f, nullptr, nullptr);

    dim3 ga((TTOT + AQ - 1) / AQ, NH, BSZ);       // (67, 8, 2)
    attn_kernel<<<ga, 256, ATTN_SMEM_BYTES>>>(pq, pk, pval, psidx, pscnt, po);

    gemm_kernel<0><<<gq, 256>>>(po, Wo, bo, pdelta, MROWS, CH, CH, 1.0f, nullptr, nullptr);

    dim3 gg1(CH / 2 / GBN, (MROWS + GBM - 1) / GBM);  // (1, 134)
    gemm_kernel<2><<<gg1, 256>>>(pv, Wg1, bg1, pg1, MROWS, CH / 2, CH, 1.0f, nullptr, nullptr);

    gemm_kernel<3><<<gq, 256>>>(pg1, Wg2, bg2, pnv, MROWS, CH, CH / 2, 1.0f, pv, pdelta);

    for (int lv = 0; lv < 5; lv++) {
        dim3 grid((hw[lv] + 31) / 32, CH / 32, BSZ);
        scatter_kernel<<<grid, tb>>>(pnv, out, hw[lv], st[lv], ob[lv]);
    }
}

// round 10
// speedup vs baseline: 2.4749x; 1.0013x over previous
#include <cuda_runtime.h>
#include <math.h>

#define BSZ   2
#define CH    256
#define SCTX  1024
#define NH    8
#define HD    32
#define TTOT  8525

typedef unsigned long long ull;

// ---- f32x2 packed math helpers (Blackwell FFMA2 path) ------------------------
__device__ __forceinline__ void fma2(ull& d, ull a, ull b) {
    asm("fma.rn.f32x2 %0, %1, %2, %0;" : "+l"(d) : "l"(a), "l"(b));
}
__device__ __forceinline__ void mul2(ull& d, ull a) {
    asm("mul.rn.f32x2 %0, %0, %1;" : "+l"(d) : "l"(a));
}
__device__ __forceinline__ ull bcast2(float f) {
    ull d; unsigned u = __float_as_uint(f);
    asm("mov.b64 %0, {%1, %1};" : "=l"(d) : "r"(u));
    return d;
}
__device__ __forceinline__ ull pack2(float lo, float hi) {
    ull d; unsigned a = __float_as_uint(lo), b = __float_as_uint(hi);
    asm("mov.b64 %0, {%1, %2};" : "=l"(d) : "r"(a), "r"(b));
    return d;
}
__device__ __forceinline__ float2 unpack2(ull v) {
    unsigned lo, hi;
    asm("mov.b64 {%0, %1}, %2;" : "=r"(lo), "=r"(hi) : "l"(v));
    return make_float2(__uint_as_float(lo), __uint_as_float(hi));
}

// ---------------- scratch (__device__ globals; no runtime allocation) --------
__device__ float g_v    [BSZ * TTOT * CH];
__device__ float g_vn   [BSZ * TTOT * CH];
__device__ float g_q    [BSZ * TTOT * CH];
__device__ float g_cn   [BSZ * SCTX * CH];
__device__ float g_k    [BSZ * SCTX * CH];
__device__ float g_val  [BSZ * SCTX * CH];
__device__ float g_o    [BSZ * TTOT * CH];
__device__ float g_delta[BSZ * TTOT * CH];
__device__ float g_g1   [BSZ * TTOT * (CH / 2)];
__device__ float g_nv   [BSZ * TTOT * CH];
__device__ int   g_sidx [BSZ * SCTX];
__device__ int   g_scnt [BSZ];

// ---------------- gather: (b, c, hw) -> v (b, t, c), tiled transpose ---------
__global__ void gather_kernel(const float* __restrict__ in, float* __restrict__ v,
                              int hw, int tstart)
{
    __shared__ float tile[32][33];
    int b   = blockIdx.z;
    int ch0 = blockIdx.y * 32;
    int p0  = blockIdx.x * 32;
    int tx = threadIdx.x, ty = threadIdx.y;   // 32 x 8
#pragma unroll
    for (int i = 0; i < 4; i++) {
        int ch = ch0 + ty + i * 8;
        int p  = p0 + tx;
        if (p < hw)
            tile[ty + i * 8][tx] = in[((size_t)(b * CH + ch)) * hw + p];
    }
    __syncthreads();
#pragma unroll
    for (int i = 0; i < 4; i++) {
        int p  = p0 + ty + i * 8;
        int ch = ch0 + tx;
        if (p < hw)
            v[((size_t)(b * TTOT + tstart + p)) * CH + ch] = tile[tx][ty + i * 8];
    }
}

// ---------------- scatter: nv (b, t, c) -> out level block (b, c, hw) --------
__global__ void scatter_kernel(const float* __restrict__ nv, float* __restrict__ out,
                               int hw, int tstart, size_t obase)
{
    __shared__ float tile[32][33];
    int b   = blockIdx.z;
    int ch0 = blockIdx.y * 32;
    int p0  = blockIdx.x * 32;
    int tx = threadIdx.x, ty = threadIdx.y;
#pragma unroll
    for (int i = 0; i < 4; i++) {
        int p  = p0 + ty + i * 8;
        int ch = ch0 + tx;
        if (p < hw)
            tile[ty + i * 8][tx] = nv[((size_t)(b * TTOT + tstart + p)) * CH + ch];
    }
    __syncthreads();
#pragma unroll
    for (int i = 0; i < 4; i++) {
        int ch = ch0 + ty + i * 8;
        int p  = p0 + tx;
        if (p < hw)
            out[obase + ((size_t)(b * CH + ch)) * hw + p] = tile[tx][ty + i * 8];
    }
}

// ---------------- layernorm over last dim (256), one block per row -----------
__global__ void ln_kernel(const float* __restrict__ x, const float* __restrict__ gg,
                          const float* __restrict__ bb, float* __restrict__ y)
{
    int row = blockIdx.x;
    int tid = threadIdx.x;          // 256 threads
    float v = x[(size_t)row * CH + tid];
    float s = v, sq = v * v;
#pragma unroll
    for (int o = 16; o > 0; o >>= 1) {
        s  += __shfl_xor_sync(0xffffffffu, s,  o);
        sq += __shfl_xor_sync(0xffffffffu, sq, o);
    }
    __shared__ float ss[8], ssq[8];
    int w = tid >> 5, l = tid & 31;
    if (l == 0) { ss[w] = s; ssq[w] = sq; }
    __syncthreads();
    if (w == 0) {
        float s2 = ss[l & 7], q2 = ssq[l & 7];
#pragma unroll
        for (int o = 4; o > 0; o >>= 1) {
            s2 += __shfl_xor_sync(0xffffffffu, s2, o);
            q2 += __shfl_xor_sync(0xffffffffu, q2, o);
        }
        if (l == 0) { ss[0] = s2; ssq[0] = q2; }
    }
    __syncthreads();
    float mean = ss[0] * (1.0f / CH);
    float var  = ssq[0] * (1.0f / CH) - mean * mean;
    y[(size_t)row * CH + tid] = (v - mean) * rsqrtf(var + 1e-5f) * gg[tid] + bb[tid];
}

// ---------------- mask compaction: list of valid s per batch -----------------
__global__ void compact_kernel(const int* __restrict__ mask, int* __restrict__ sidx,
                               int* __restrict__ scnt)
{
    int b = blockIdx.x, t = threadIdx.x;         // 1024 threads
    __shared__ int wsum[32];
    int m = mask[b * SCTX + t];
    unsigned bal = __ballot_sync(0xffffffffu, m != 0);
    int lane = t & 31, w = t >> 5;
    if (lane == 0) wsum[w] = __popc(bal);
    __syncthreads();
    if (w == 0) {
        int v = wsum[lane];
#pragma unroll
        for (int o = 1; o < 32; o <<= 1) {
            int n = __shfl_up_sync(0xffffffffu, v, o);
            if (lane >= o) v += n;
        }
        wsum[lane] = v;                           // inclusive scan
    }
    __syncthreads();
    int base = (w == 0) ? 0 : wsum[w - 1];
    int pre  = __popc(bal & ((1u << lane) - 1u));
    if (m) sidx[b * SCTX + base + pre] = t;
    if (t == 0) scnt[b] = wsum[31];
}

// ---------------- generic GEMM: C = epi(A @ W + bias), 128x64, FFMA2 ---------
// EPI 0: +bias   1: (+bias)*scale   2: relu(+bias)   3: vres + tanh(+bias)*dres
#define GBM 128
#define GBN 64
#define GBK 32

template <int EPI>
__global__ void __launch_bounds__(256)
gemm_kernel(const float* __restrict__ A, const float* __restrict__ W,
            const float* __restrict__ bias, float* __restrict__ Cm,
            int M, int N, int K, float scale,
            const float* __restrict__ vres, const float* __restrict__ dres)
{
    __shared__ __align__(16) float Ast[GBK][GBM + 4];   // transposed A: [k][row]
    __shared__ __align__(16) float Bs [GBK][GBN + 4];
    int bm  = blockIdx.y * GBM;
    int bn  = blockIdx.x * GBN;
    int tid = threadIdx.x;                 // 256
    int trow = tid >> 4;                   // 0..15 -> rows trow*8..+7
    int tcol = tid & 15;                   // 0..15 -> cols tcol*4..+3
    ull acc2[4][4] = {};                   // row-pair x col, packed f32x2
    for (int k0 = 0; k0 < K; k0 += GBK) {
#pragma unroll
        for (int e = 0; e < 4; e++) {
            int lin = tid + e * 256;
            int r = lin >> 3, c4 = (lin & 7) << 2;
            int gr = bm + r;
            float4 av = make_float4(0.f, 0.f, 0.f, 0.f);
            if (gr < M) av = *(const float4*)&A[(size_t)gr * K + k0 + c4];
            Ast[c4 + 0][r] = av.x;
            Ast[c4 + 1][r] = av.y;
            Ast[c4 + 2][r] = av.z;
            Ast[c4 + 3][r] = av.w;
        }
#pragma unroll
        for (int e = 0; e < 2; e++) {
            int lin = tid + e * 256;
            int r = lin >> 4, c4 = (lin & 15) << 2;
            *(float4*)&Bs[r][c4] = *(const float4*)&W[(size_t)(k0 + r) * N + bn + c4];
        }
        __syncthreads();
#pragma unroll
        for (int k = 0; k < GBK; k++) {
            ulonglong2 aL = *(const ulonglong2*)&Ast[k][trow * 8];      // rows (0,1)(2,3)
            ulonglong2 aH = *(const ulonglong2*)&Ast[k][trow * 8 + 4];  // rows (4,5)(6,7)
            float4 bv = *(const float4*)&Bs[k][tcol * 4];
            ull b0 = bcast2(bv.x), b1 = bcast2(bv.y);
            ull b2 = bcast2(bv.z), b3 = bcast2(bv.w);
            fma2(acc2[0][0], aL.x, b0); fma2(acc2[0][1], aL.x, b1);
            fma2(acc2[0][2], aL.x, b2); fma2(acc2[0][3], aL.x, b3);
            fma2(acc2[1][0], aL.y, b0); fma2(acc2[1][1], aL.y, b1);
            fma2(acc2[1][2], aL.y, b2); fma2(acc2[1][3], aL.y, b3);
            fma2(acc2[2][0], aH.x, b0); fma2(acc2[2][1], aH.x, b1);
            fma2(acc2[2][2], aH.x, b2); fma2(acc2[2][3], aH.x, b3);
            fma2(acc2[3][0], aH.y, b0); fma2(acc2[3][1], aH.y, b1);
            fma2(acc2[3][2], aH.y, b2); fma2(acc2[3][3], aH.y, b3);
        }
        __syncthreads();
    }
    float4 bb = *(const float4*)&bias[bn + tcol * 4];
#pragma unroll
    for (int rp = 0; rp < 4; rp++) {
        float2 c0 = unpack2(acc2[rp][0]);
        float2 c1 = unpack2(acc2[rp][1]);
        float2 c2 = unpack2(acc2[rp][2]);
        float2 c3 = unpack2(acc2[rp][3]);
        float rowv[2][4] = {{c0.x, c1.x, c2.x, c3.x},
                            {c0.y, c1.y, c2.y, c3.y}};
#pragma unroll
        for (int hh = 0; hh < 2; hh++) {
            int gr = bm + trow * 8 + rp * 2 + hh;
            if (gr >= M) continue;
            float vv[4] = {rowv[hh][0] + bb.x, rowv[hh][1] + bb.y,
                           rowv[hh][2] + bb.z, rowv[hh][3] + bb.w};
#pragma unroll
            for (int j = 0; j < 4; j++) {
                int gc = bn + tcol * 4 + j;
                float val = vv[j];
                if (EPI == 1) val *= scale;
                if (EPI == 2) val = fmaxf(val, 0.0f);
                if (EPI == 3) {
                    size_t ridx = (size_t)gr * 256 + gc;   // vres/dres have 256 cols
                    val = vres[ridx] + tanhf(val) * dres[ridx];
                }
                vv[j] = val;
            }
            *(float4*)&Cm[(size_t)gr * N + bn + tcol * 4] =
                make_float4(vv[0], vv[1], vv[2], vv[3]);
        }
    }
}

// ---------------- flash attention over compacted valid keys, FFMA2 -----------
#define AQ 128
#define AS 64
// dynamic smem layout (floats):
//   Qst [32][132]   off 0       (transposed Q: [k][row])
//   Kst [32][68]    off 4224    (transposed K: [k][s])
//   Vs  [64][36]    off 6400    (V row-major:  [s][d])
//   Lst [64][132]   off 8704    (logits/probs TRANSPOSED: [s][row])
//   rowm[128] off 17152  rowl[128] off 17280  rowfac[128] off 17408
#define ATTN_SMEM_FLOATS 17536
#define ATTN_SMEM_BYTES  (ATTN_SMEM_FLOATS * 4)

__global__ void __launch_bounds__(256)
attn_kernel(const float* __restrict__ Qb, const float* __restrict__ Kb,
            const float* __restrict__ Vb, const int* __restrict__ sidxp,
            const int* __restrict__ scnt, float* __restrict__ Ob)
{
    extern __shared__ __align__(16) float sm[];
    float* Qst    = sm;            // stride 132
    float* Kst    = sm + 4224;     // stride 68
    float* Vs     = sm + 6400;     // stride 36
    float* Lst    = sm + 8704;     // stride 132, [s][row]
    float* rowm   = sm + 17152;
    float* rowl   = sm + 17280;
    float* rowfac = sm + 17408;

    int b  = blockIdx.z;
    int h  = blockIdx.y;
    int t0 = blockIdx.x * AQ;
    int tid = threadIdx.x;               // 256
    int trow = tid >> 4;                 // 0..15
    int tcol = tid & 15;                 // 0..15
    int cnt = scnt[b];

    if (tid < AQ) { rowm[tid] = -INFINITY; rowl[tid] = 0.0f; }

    // load Q tile transposed: [k][row]
#pragma unroll
    for (int e = 0; e < 4; e++) {
        int lin = tid + e * 256;
        int r = lin >> 3, c4 = (lin & 7) << 2;
        int t = t0 + r;
        float4 qv = make_float4(0.f, 0.f, 0.f, 0.f);
        if (t < TTOT) qv = *(const float4*)&Qb[((size_t)(b * TTOT + t)) * CH + h * HD + c4];
        Qst[(c4 + 0) * 132 + r] = qv.x;
        Qst[(c4 + 1) * 132 + r] = qv.y;
        Qst[(c4 + 2) * 132 + r] = qv.z;
        Qst[(c4 + 3) * 132 + r] = qv.w;
    }

    ull acc2[4][2] = {};   // row-pair x dim, packed over rows

    for (int s0 = 0; s0 < cnt; s0 += AS) {
        int rem = cnt - s0;
        __syncthreads();   // protect Kst/Vs/Lst reuse + first-iter Q/init visibility

        // load K (transposed) / V (row-major) chunk via index list
#pragma unroll
        for (int e = 0; e < 2; e++) {
            int lin = tid + e * 256;
            int sr = lin >> 3, c4 = (lin & 7) << 2;
            int sidx = (sr < rem) ? sidxp[b * SCTX + s0 + sr] : 0;
            size_t gbase = ((size_t)(b * SCTX + sidx)) * CH + h * HD + c4;
            float4 kv = *(const float4*)&Kb[gbase];
            float4 vv = *(const float4*)&Vb[gbase];
            Kst[(c4 + 0) * 68 + sr] = kv.x;
            Kst[(c4 + 1) * 68 + sr] = kv.y;
            Kst[(c4 + 2) * 68 + sr] = kv.z;
            Kst[(c4 + 3) * 68 + sr] = kv.w;
            *(float4*)&Vs[sr * 36 + c4] = vv;
        }
        __syncthreads();

        // logits: 8x4 micro-tile per thread, packed row pairs
        ull lg2[4][4] = {};
#pragma unroll
        for (int k = 0; k < HD; k++) {
            ulonglong2 aL = *(const ulonglong2*)&Qst[k * 132 + trow * 8];
            ulonglong2 aH = *(const ulonglong2*)&Qst[k * 132 + trow * 8 + 4];
            float4 kv = *(const float4*)&Kst[k * 68 + tcol * 4];
            ull b0 = bcast2(kv.x), b1 = bcast2(kv.y);
            ull b2 = bcast2(kv.z), b3 = bcast2(kv.w);
            fma2(lg2[0][0], aL.x, b0); fma2(lg2[0][1], aL.x, b1);
            fma2(lg2[0][2], aL.x, b2); fma2(lg2[0][3], aL.x, b3);
            fma2(lg2[1][0], aL.y, b0); fma2(lg2[1][1], aL.y, b1);
            fma2(lg2[1][2], aL.y, b2); fma2(lg2[1][3], aL.y, b3);
            fma2(lg2[2][0], aH.x, b0); fma2(lg2[2][1], aH.x, b1);
            fma2(lg2[2][2], aH.x, b2); fma2(lg2[2][3], aH.x, b3);
            fma2(lg2[3][0], aH.y, b0); fma2(lg2[3][1], aH.y, b1);
            fma2(lg2[3][2], aH.y, b2); fma2(lg2[3][3], aH.y, b3);
        }
        // clip + mask, store TRANSPOSED: Lst[s][row]
#pragma unroll
        for (int j = 0; j < 4; j++) {
            float mj = (s0 + tcol * 4 + j < cnt) ? 1.0f : -9e15f;
            ulonglong2 stL, stH;
            {
                float2 c = unpack2(lg2[0][j]);
                c.x = fminf(fmaxf(c.x, -50000.0f), 50000.0f) + mj;
                c.y = fminf(fmaxf(c.y, -50000.0f), 50000.0f) + mj;
                stL.x = pack2(c.x, c.y);
            }
            {
                float2 c = unpack2(lg2[1][j]);
                c.x = fminf(fmaxf(c.x, -50000.0f), 50000.0f) + mj;
                c.y = fminf(fmaxf(c.y, -50000.0f), 50000.0f) + mj;
                stL.y = pack2(c.x, c.y);
            }
            {
                float2 c = unpack2(lg2[2][j]);
                c.x = fminf(fmaxf(c.x, -50000.0f), 50000.0f) + mj;
                c.y = fminf(fmaxf(c.y, -50000.0f), 50000.0f) + mj;
                stH.x = pack2(c.x, c.y);
            }
            {
                float2 c = unpack2(lg2[3][j]);
                c.x = fminf(fmaxf(c.x, -50000.0f), 50000.0f) + mj;
                c.y = fminf(fmaxf(c.y, -50000.0f), 50000.0f) + mj;
                stH.y = pack2(c.x, c.y);
            }
            int sIdx = tcol * 4 + j;
            *(ulonglong2*)&Lst[sIdx * 132 + trow * 8]     = stL;
            *(ulonglong2*)&Lst[sIdx * 132 + trow * 8 + 4] = stH;
        }
        __syncthreads();

        // online softmax over transposed Lst: 2 threads per row
        {
            int r = tid >> 1, half = tid & 1;
            float v[32];
#pragma unroll
            for (int q = 0; q < 32; q++)
                v[q] = Lst[(half * 32 + q) * 132 + r];
            float mold = rowm[r];
            float cmax = -INFINITY;
#pragma unroll
            for (int j = 0; j < 32; j++) cmax = fmaxf(cmax, v[j]);
            cmax = fmaxf(cmax, __shfl_xor_sync(0xffffffffu, cmax, 1));
            float newm = fmaxf(mold, cmax);
            float csum = 0.0f;
#pragma unroll
            for (int j = 0; j < 32; j++) {
                v[j] = __expf(v[j] - newm);
                csum += v[j];
            }
#pragma unroll
            for (int q = 0; q < 32; q++)
                Lst[(half * 32 + q) * 132 + r] = v[q];
            csum += __shfl_xor_sync(0xffffffffu, csum, 1);
            float fac = __expf(mold - newm);
            if (half == 0) {
                rowfac[r] = fac;
                rowl[r]   = rowl[r] * fac + csum;
                rowm[r]   = newm;
            }
        }
        __syncthreads();

        // PV: packed row-pairs, dims d0=tcol*2, d1=tcol*2+1
        {
#pragma unroll
            for (int rp = 0; rp < 4; rp++) {
                ull fpair = *(const ull*)&rowfac[trow * 8 + rp * 2];
                mul2(acc2[rp][0], fpair);
                mul2(acc2[rp][1], fpair);
            }
#pragma unroll 8
            for (int s = 0; s < AS; s++) {
                ulonglong2 pL = *(const ulonglong2*)&Lst[s * 132 + trow * 8];
                ulonglong2 pH = *(const ulonglong2*)&Lst[s * 132 + trow * 8 + 4];
                float2 v2 = *(const float2*)&Vs[s * 36 + tcol * 2];
                ull vb0 = bcast2(v2.x), vb1 = bcast2(v2.y);
                fma2(acc2[0][0], pL.x, vb0); fma2(acc2[0][1], pL.x, vb1);
                fma2(acc2[1][0], pL.y, vb0); fma2(acc2[1][1], pL.y, vb1);
                fma2(acc2[2][0], pH.x, vb0); fma2(acc2[2][1], pH.x, vb1);
                fma2(acc2[3][0], pH.y, vb0); fma2(acc2[3][1], pH.y, vb1);
            }
        }
    }

#pragma unroll
    for (int rp = 0; rp < 4; rp++) {
        float2 d0 = unpack2(acc2[rp][0]);   // dim d0: rows (2rp, 2rp+1)
        float2 d1 = unpack2(acc2[rp][1]);
        int rowA = trow * 8 + rp * 2;
        int tA = t0 + rowA, tB = tA + 1;
        if (tA < TTOT) {
            float inv = 1.0f / rowl[rowA];
            *(float2*)&Ob[((size_t)(b * TTOT + tA)) * CH + h * HD + tcol * 2] =
                make_float2(d0.x * inv, d1.x * inv);
        }
        if (tB < TTOT) {
            float inv = 1.0f / rowl[rowA + 1];
            *(float2*)&Ob[((size_t)(b * TTOT + tB)) * CH + h * HD + tcol * 2] =
                make_float2(d0.y * inv, d1.y * inv);
        }
    }
}

// ---------------- launch ------------------------------------------------------
extern "C" void kernel_launch(void* const* d_in, const int* in_sizes, int n_in,
                              void* d_out, int out_size)
{
    const float* qin[5];
    for (int i = 0; i < 5; i++) qin[i] = (const float*)d_in[i];
    const float* cache  = (const float*)d_in[5];
    const int*   mask   = (const int*)d_in[6];
    const float* ln_v_g = (const float*)d_in[7];
    const float* ln_v_b = (const float*)d_in[8];
    const float* ln_c_g = (const float*)d_in[9];
    const float* ln_c_b = (const float*)d_in[10];
    const float* Wv  = (const float*)d_in[11];
    const float* bv  = (const float*)d_in[12];
    const float* Wc  = (const float*)d_in[13];
    const float* bc  = (const float*)d_in[14];
    const float* Wvc = (const float*)d_in[15];
    const float* bvc = (const float*)d_in[16];
    const float* Wo  = (const float*)d_in[17];
    const float* bo  = (const float*)d_in[18];
    const float* Wg1 = (const float*)d_in[19];
    const float* bg1 = (const float*)d_in[20];
    const float* Wg2 = (const float*)d_in[21];
    const float* bg2 = (const float*)d_in[22];
    float* out = (float*)d_out;

    float *pv, *pvn, *pq, *pcn, *pk, *pval, *po, *pdelta, *pg1, *pnv;
    int *psidx, *pscnt;
    cudaGetSymbolAddress((void**)&pv,     g_v);
    cudaGetSymbolAddress((void**)&pvn,    g_vn);
    cudaGetSymbolAddress((void**)&pq,     g_q);
    cudaGetSymbolAddress((void**)&pcn,    g_cn);
    cudaGetSymbolAddress((void**)&pk,     g_k);
    cudaGetSymbolAddress((void**)&pval,   g_val);
    cudaGetSymbolAddress((void**)&po,     g_o);
    cudaGetSymbolAddress((void**)&pdelta, g_delta);
    cudaGetSymbolAddress((void**)&pg1,    g_g1);
    cudaGetSymbolAddress((void**)&pnv,    g_nv);
    cudaGetSymbolAddress((void**)&psidx,  g_sidx);
    cudaGetSymbolAddress((void**)&pscnt,  g_scnt);

    cudaFuncSetAttribute(attn_kernel,
                         cudaFuncAttributeMaxDynamicSharedMemorySize, ATTN_SMEM_BYTES);

    static const int    hw[5] = {6400, 1600, 400, 100, 25};
    static const int    st[5] = {0, 6400, 8000, 8400, 8500};
    static const size_t ob[5] = {0, 3276800, 4096000, 4300800, 4352000};

    const int MROWS = BSZ * TTOT;               // 17050
    const int CROWS = BSZ * SCTX;               // 2048
    const float scale = 0.1767766952966369f;    // 32^-0.5

    dim3 tb(32, 8);
    for (int lv = 0; lv < 5; lv++) {
        dim3 grid((hw[lv] + 31) / 32, CH / 32, BSZ);
        gather_kernel<<<grid, tb>>>(qin[lv], pv, hw[lv], st[lv]);
    }

    compact_kernel<<<BSZ, 1024>>>(mask, psidx, pscnt);

    ln_kernel<<<MROWS, 256>>>(pv, ln_v_g, ln_v_b, pvn);
    ln_kernel<<<CROWS, 256>>>(cache, ln_c_g, ln_c_b, pcn);

    dim3 gq(CH / GBN, (MROWS + GBM - 1) / GBM);   // (4, 134)
    dim3 gc(CH / GBN, CROWS / GBM);               // (4, 16)
    gemm_kernel<1><<<gq, 256>>>(pvn, Wv, bv, pq, MROWS, CH, CH, scale, nullptr, nullptr);
    gemm_kernel<0><<<gc, 256>>>(pcn, Wc,  bc,  pk,   CROWS, CH, CH, 1.0f, nullptr, nullptr);
    gemm_kernel<0><<<gc, 256>>>(pcn, Wvc, bvc, pval, CROWS, CH, CH, 1.0f, nullptr, nullptr);

    dim3 ga((TTOT + AQ - 1) / AQ, NH, BSZ);       // (67, 8, 2)
    attn_kernel<<<ga, 256, ATTN_SMEM_BYTES>>>(pq, pk, pval, psidx, pscnt, po);

    gemm_kernel<0><<<gq, 256>>>(po, Wo, bo, pdelta, MROWS, CH, CH, 1.0f, nullptr, nullptr);

    dim3 gg1(CH / 2 / GBN, (MROWS + GBM - 1) / GBM);  // (1, 134)
    gemm_kernel<2><<<gg1, 256>>>(pv, Wg1, bg1, pg1, MROWS, CH / 2, CH, 1.0f, nullptr, nullptr);

    gemm_kernel<3><<<gq, 256>>>(pg1, Wg2, bg2, pnv, MROWS, CH, CH / 2, 1.0f, pv, pdelta);

    for (int lv = 0; lv < 5; lv++) {
        dim3 grid((hw[lv] + 31) / 32, CH / 32, BSZ);
        scatter_kernel<<<grid, tb>>>(pnv, out, hw[lv], st[lv], ob[lv]);
    }
}